// round 11
// baseline (speedup 1.0000x reference)
#include <cuda_runtime.h>
#include <cuda_fp16.h>
#include <math.h>
#include <stdint.h>

#define NUM_EMBED 8192
#define EMBED_DIM 64
#define BB 8
#define HH 64
#define WW 64
#define N_TOK   (BB*HH*WW)            /* 32768 */
#define N_ELEM  (BB*EMBED_DIM*HH*WW)  /* 2097152 */
#define HW      (HH*WW)               /* 4096 */
#define N_PART  1024

#define M_CTA   128                   /* tokens per CTA (stage 1) */
#define TN      128                   /* codes per tile */
#define N_TILES (NUM_EMBED / TN)      /* 64 */
#define NT1     256                   /* stage-1 threads (8 warps) */
#define NT2     512                   /* stage-2 threads */
#define N_MT    (N_TOK / 256)         /* 128 token-tiles for rescan */

// stage-1 SMEM (from 1024-aligned base):
//   A0  @ 0     : 128 rows x 128B (fp16 z, swizzled)   16384
//   B   @ 16384 : 3 bufs x [128 x 128B]                49152
//   TAB @ 65536 : 128 x 2 float4                        4096
#define OFF_B    16384
#define OFF_TAB  65536
#define SMEM1_BYTES (OFF_TAB + 4096 + 1024)

// stage-2 SMEM:
//   A0 @ 0, A1 @ 32768 (256 rows x 128B each)
//   B  @ 65536 : 2 bufs x 2 terms x 16KB = 65536
//   TAB@ 131072: 256 x 2 float2 = 4096; TOK @ 135168: 1KB
#define OFF2_A1  32768
#define OFF2_B   65536
#define OFF2_TAB 131072
#define OFF2_TOK 135168
#define SMEM2_BYTES (OFF2_TOK + 1024 + 1024)

#define SWZ(o) ((o) ^ (((o) >> 3) & 0x70))

// ---------------------------------------------------------------------------
// device scratch
// ---------------------------------------------------------------------------
__device__ __align__(16) __half g_e0[NUM_EMBED * EMBED_DIM];
__device__ __align__(16) __half g_e1[NUM_EMBED * EMBED_DIM];
__device__ __align__(16) float  g_enf[NUM_EMBED * EMBED_DIM];
__device__ int   g_idx[N_TOK];
__device__ int   g_flist[N_TOK];
__device__ int   g_nflag;
__device__ unsigned long long g_best[N_TOK];
__device__ int   g_cnt[N_MT];
__device__ int   g_hist[NUM_EMBED];
__device__ float g_partial[N_PART];

// ---------------------------------------------------------------------------
// asm helpers (plain sm_80+ only)
// ---------------------------------------------------------------------------
__device__ __forceinline__ uint32_t smem_u32(const void* p) {
    uint32_t a;
    asm("{ .reg .u64 t; cvta.to.shared.u64 t, %1; cvt.u32.u64 %0, t; }" : "=r"(a) : "l"(p));
    return a;
}
#define LDSM_X4(r, addr)                                                         \
    asm volatile("ldmatrix.sync.aligned.m8n8.x4.shared.b16 {%0,%1,%2,%3}, [%4];" \
        : "=r"((r)[0]), "=r"((r)[1]), "=r"((r)[2]), "=r"((r)[3]) : "r"(addr))

#define MMA_16816(c, a, b0, b1)                                                  \
    asm volatile("mma.sync.aligned.m16n8k16.row.col.f32.f16.f16.f32 "            \
        "{%0,%1,%2,%3}, {%4,%5,%6,%7}, {%8,%9}, {%0,%1,%2,%3};"                  \
        : "+f"((c)[0]), "+f"((c)[1]), "+f"((c)[2]), "+f"((c)[3])                 \
        : "r"((a)[0]), "r"((a)[1]), "r"((a)[2]), "r"((a)[3]), "r"(b0), "r"(b1))

#define CP_ASYNC16(saddr, gptr)                                                  \
    asm volatile("cp.async.cg.shared.global [%0], [%1], 16;" :: "r"(saddr), "l"(gptr))
#define CP_COMMIT()  asm volatile("cp.async.commit_group;")
#define CP_WAIT1()   asm volatile("cp.async.wait_group 1;")
#define CP_WAIT0()   asm volatile("cp.async.wait_group 0;")

__device__ __forceinline__ uint32_t fkey(float v) {
    uint32_t u = __float_as_uint(v);
    return (u & 0x80000000u) ? ~u : (u | 0x80000000u);
}

// ---------------------------------------------------------------------------
// Kernel 1: zero scratch + normalize codebook -> fp16 x2 split + fp32
// ---------------------------------------------------------------------------
__global__ void vq_prep_embed(const float* __restrict__ emb) {
    int gid = blockIdx.x * 256 + threadIdx.x;
    if (threadIdx.x < 8) g_hist[blockIdx.x * 8 + threadIdx.x] = 0;
    if (gid < N_TOK) g_best[gid] = 0ull;
    if (gid < N_MT) g_cnt[gid] = 0;
    if (gid == 0) g_nflag = 0;

    int wid  = gid >> 5;
    int lane = threadIdx.x & 31;
    if (wid >= NUM_EMBED) return;
    const float* row = emb + wid * EMBED_DIM;
    float x0 = row[lane];
    float x1 = row[lane + 32];
    float s = x0 * x0 + x1 * x1;
    #pragma unroll
    for (int o = 16; o > 0; o >>= 1) s += __shfl_xor_sync(0xFFFFFFFFu, s, o);
    float inv = 1.0f / sqrtf(s);
    #pragma unroll
    for (int h = 0; h < 2; h++) {
        int c = lane + h * 32;
        float xn = (h ? x1 : x0) * inv;
        __half h0 = __float2half(xn);
        __half h1 = __float2half(xn - __half2float(h0));
        g_e0[wid * EMBED_DIM + c]  = h0;
        g_e1[wid * EMBED_DIM + c]  = h1;
        g_enf[wid * EMBED_DIM + c] = xn;
    }
}

// ---------------------------------------------------------------------------
// Kernel 2 (stage 1): 1-term fp16 GEMM + pairwise top-2 + certificate.
// 256 threads = 8 warps, 4(M) x 2(N). 3-buffer cp.async ring: ONE sync/tile.
// ---------------------------------------------------------------------------
__global__ __launch_bounds__(NT1, 2)
void vq_argmax_mma(const float* __restrict__ z, float* __restrict__ idx_out_f) {
    extern __shared__ char dsm_raw[];
    const uint32_t raw   = smem_u32(dsm_raw);
    const uint32_t abase = (raw + 1023u) & ~1023u;
    char* sm = dsm_raw + (abase - raw);

    const int tid    = threadIdx.x;
    const int wid    = tid >> 5;
    const int lane   = tid & 31;
    const int warp_m = wid & 3;
    const int warp_n = wid >> 2;
    const int wm0    = warp_m * 32;
    const int cn0    = warp_n * 64;
    const int grp    = lane >> 3;

    const int m0  = blockIdx.x * M_CTA;
    const int b   = m0 >> 12;
    const int hw0 = m0 & 4095;

    auto load_b = [&](int t, int p) {
        const int n0 = t * TN;
        const uint32_t sb = abase + OFF_B + p * 16384;
        #pragma unroll
        for (int q = 0; q < 4; q++) {
            int i  = tid + q * NT1;        // 0..1023
            int r  = i >> 3;
            int ch = i & 7;
            CP_ASYNC16(sb + SWZ(r * 128 + ch * 16),
                       g_e0 + (n0 + r) * EMBED_DIM + ch * 8);
        }
    };

    load_b(0, 0);
    CP_COMMIT();
    load_b(1, 1);
    CP_COMMIT();

    // prologue: z tile -> fp16 A0 (swizzled)
    {
        const float* zb = z + b * (EMBED_DIM * HW) + hw0;
        #pragma unroll
        for (int q = 0; q < 8; q++) {
            int i  = tid + q * NT1;        // 0..2047
            int c  = i >> 5;
            int m4 = (i & 31) << 2;
            float4 v = *(const float4*)(zb + c * HW + m4);
            float xs[4] = {v.x, v.y, v.z, v.w};
            #pragma unroll
            for (int e = 0; e < 4; e++)
                *(__half*)(sm + SWZ((m4 + e) * 128 + c * 2)) = __float2half(xs[e]);
        }
    }

    float v1[4], v2[4];
    int   vi[4];
    #pragma unroll
    for (int s = 0; s < 4; s++) { v1[s] = -3.0e38f; v2[s] = -3.0e38f; vi[s] = 0x7FFFFFFF; }

    const int a_row  = wm0 + (grp & 1) * 8 + (lane & 7);
    const int b_rowL = cn0 + (grp & 1) * 8 + (lane & 7);
    const int k_off  = (grp >> 1) * 8;

    for (int t = 0; t < N_TILES; t++) {
        const int n0 = t * TN;

        // tile t data ready (pending <= 1 leaves only tile t+1 in flight)
        if (t + 1 < N_TILES) { CP_WAIT1(); } else { CP_WAIT0(); }
        __syncthreads();   // all warps see tile t data; all done reading buf (t+2)%3

        if (t + 2 < N_TILES) {
            load_b(t + 2, (t + 2) % 3);
            CP_COMMIT();
        }

        float acc[2][8][4];
        #pragma unroll
        for (int i = 0; i < 2; i++)
            #pragma unroll
            for (int j = 0; j < 8; j++)
                #pragma unroll
                for (int q = 0; q < 4; q++) acc[i][j][q] = 0.0f;

        const uint32_t bbuf = abase + OFF_B + (t % 3) * 16384;
        #pragma unroll
        for (int ks = 0; ks < 4; ks++) {
            const int kb = ks * 16 + k_off;
            uint32_t a0f[2][4];
            #pragma unroll
            for (int i = 0; i < 2; i++)
                LDSM_X4(a0f[i], abase + SWZ((a_row + i * 16) * 128 + kb * 2));
            #pragma unroll
            for (int j2 = 0; j2 < 4; j2++) {
                uint32_t b0r[4];
                LDSM_X4(b0r, bbuf + SWZ((b_rowL + j2 * 16) * 128 + kb * 2));
                #pragma unroll
                for (int sub = 0; sub < 2; sub++)
                    #pragma unroll
                    for (int i = 0; i < 2; i++)
                        MMA_16816(acc[i][j2 * 2 + sub], a0f[i], b0r[sub], b0r[2 + sub]);
            }
        }

        // pairwise hi/lo top-2 (first-max-on-tie preserved)
        #pragma unroll
        for (int i = 0; i < 2; i++) {
            #pragma unroll
            for (int j = 0; j < 8; j++) {
                int cbase = n0 + cn0 + j * 8 + (lane & 3) * 2;
                #pragma unroll
                for (int h = 0; h < 2; h++) {
                    int s = i * 2 + h;
                    float va = acc[i][j][2 * h + 0];
                    float vb = acc[i][j][2 * h + 1];
                    float hi = fmaxf(va, vb);
                    float lo = fminf(va, vb);
                    int   hidx = (vb > va) ? (cbase + 1) : cbase;
                    if (hi > v1[s]) {
                        v2[s] = fmaxf(v1[s], lo);
                        v1[s] = hi;
                        vi[s] = hidx;
                    } else {
                        v2[s] = fmaxf(v2[s], hi);
                    }
                }
            }
        }
    }

    // quad reduce with top-2 merge
    #pragma unroll
    for (int s = 0; s < 4; s++) {
        #pragma unroll
        for (int off = 1; off < 4; off <<= 1) {
            float ov1 = __shfl_xor_sync(0xFFFFFFFFu, v1[s], off);
            int   oi1 = __shfl_xor_sync(0xFFFFFFFFu, vi[s], off);
            float ov2 = __shfl_xor_sync(0xFFFFFFFFu, v2[s], off);
            if (ov1 > v1[s] || (ov1 == v1[s] && oi1 < vi[s])) {
                v2[s] = fmaxf(fmaxf(v1[s], ov2), v2[s]);
                v1[s] = ov1; vi[s] = oi1;
            } else {
                v2[s] = fmaxf(fmaxf(v2[s], ov1), ov2);
            }
        }
    }

    __syncthreads();
    float4* table = (float4*)(sm + OFF_TAB);
    if ((lane & 3) == 0) {
        #pragma unroll
        for (int s = 0; s < 4; s++) {
            int row = wm0 + (s >> 1) * 16 + (s & 1) * 8 + (lane >> 2);
            table[row * 2 + warp_n] =
                make_float4(v1[s], __int_as_float(vi[s]), v2[s], 0.0f);
        }
    }
    __syncthreads();

    if (tid < M_CTA) {
        float4 r0 = table[tid * 2 + 0];
        float4 r1 = table[tid * 2 + 1];
        float fv2; int fi1;
        int i0 = __float_as_int(r0.y), i1 = __float_as_int(r1.y);
        if (r1.x > r0.x || (r1.x == r0.x && i1 < i0)) {
            fi1 = i1; fv2 = fmaxf(r0.x, r1.z);
        } else {
            fi1 = i0; fv2 = fmaxf(r1.x, r0.z);
        }

        // exact fp32 rescore of fi1 (z re-read, L2-hot) + ||z||^2
        const float* zb2 = z + b * (EMBED_DIM * HW) + hw0 + tid;
        const float4* er = (const float4*)(g_enf + fi1 * EMBED_DIM);
        float acc = 0.0f, accn = 0.0f;
        #pragma unroll
        for (int q = 0; q < 16; q++) {
            float4 ev = er[q];
            float z0 = zb2[(q * 4 + 0) * HW];
            float z1 = zb2[(q * 4 + 1) * HW];
            float z2 = zb2[(q * 4 + 2) * HW];
            float z3 = zb2[(q * 4 + 3) * HW];
            acc  += z0 * ev.x + z1 * ev.y + z2 * ev.z + z3 * ev.w;
            accn += z0 * z0 + z1 * z1 + z2 * z2 + z3 * z3;
        }
        float eps = 5.2e-4f * sqrtf(accn) + 1.0e-5f;

        int token = m0 + tid;
        g_idx[token] = fi1;
        if (acc > fv2 + eps) {
            atomicAdd(&g_hist[fi1], 1);
            idx_out_f[token] = (float)fi1;
        } else {
            int pos = atomicAdd(&g_nflag, 1);
            g_flist[pos] = token;
        }
    }
}

// ---------------------------------------------------------------------------
// Kernel 3 (stage 2): 3-term mma rescan of flagged tokens + inline resolve.
// grid 512 = 32 token-tiles x 16 codebook splits (512 codes each).
// The last-finishing split of each tile resolves its 256 tokens.
// ---------------------------------------------------------------------------
__global__ __launch_bounds__(NT2, 1)
void vq_rescan_mma(const float* __restrict__ z, float* __restrict__ idx_out_f) {
    const int count = g_nflag;
    const int mt = blockIdx.x >> 4;
    const int sp = blockIdx.x & 15;
    const int base = mt * 256;
    if (base >= count) return;

    extern __shared__ char dsm_raw[];
    const uint32_t raw   = smem_u32(dsm_raw);
    const uint32_t abase = (raw + 1023u) & ~1023u;
    char* sm = dsm_raw + (abase - raw);
    int* s_tok = (int*)(sm + OFF2_TOK);
    __shared__ int s_last;

    const int tid    = threadIdx.x;
    const int wid    = tid >> 5;
    const int lane   = tid & 31;
    const int warp_m = wid & 7;
    const int warp_n = wid >> 3;
    const int wm0    = warp_m * 32;
    const int cn0    = warp_n * 64;
    const int grp    = lane >> 3;
    const int nbase  = sp * 512;

    auto load_b = [&](int t, int p) {
        const int n0 = nbase + t * TN;
        const uint32_t sb = abase + OFF2_B + p * 32768;
        #pragma unroll
        for (int q = 0; q < 4; q++) {
            int i    = tid + q * NT2;
            int term = i >> 10;
            int rq   = i & 1023;
            int r    = rq >> 3;
            int ch   = rq & 7;
            const __half* src = term ? g_e1 : g_e0;
            CP_ASYNC16(sb + term * 16384 + SWZ(r * 128 + ch * 16),
                       src + (n0 + r) * EMBED_DIM + ch * 8);
        }
    };

    if (tid < 256) s_tok[tid] = g_flist[min(base + tid, count - 1)];

    load_b(0, 0);
    CP_COMMIT();
    __syncthreads();

    {
        int row  = tid >> 1;
        int half = tid & 1;
        int tok  = s_tok[row];
        const float* zb = z + (tok >> 12) * (EMBED_DIM * HW) + (tok & 4095);
        #pragma unroll
        for (int q = 0; q < 32; q++) {
            int c = half * 32 + q;
            float x = zb[c * HW];
            __half h0 = __float2half(x);
            __half h1 = __float2half(x - __half2float(h0));
            int off = SWZ(row * 128 + c * 2);
            *(__half*)(sm + off)           = h0;
            *(__half*)(sm + OFF2_A1 + off) = h1;
        }
    }
    __syncthreads();

    float bv[4];
    int   bi[4];
    #pragma unroll
    for (int s = 0; s < 4; s++) { bv[s] = -3.0e38f; bi[s] = 0x7FFFFFFF; }

    const int a_row  = wm0 + (grp & 1) * 8 + (lane & 7);
    const int b_rowL = cn0 + (grp & 1) * 8 + (lane & 7);
    const int k_off  = (grp >> 1) * 8;

    for (int t = 0; t < 4; t++) {
        const int p  = t & 1;
        const int n0 = nbase + t * TN;

        if (t + 1 < 4) {
            load_b(t + 1, (t + 1) & 1);
            CP_COMMIT();
            CP_WAIT1();
        } else {
            CP_WAIT0();
        }
        __syncthreads();

        float acc[2][8][4];
        #pragma unroll
        for (int i = 0; i < 2; i++)
            #pragma unroll
            for (int j = 0; j < 8; j++)
                #pragma unroll
                for (int q = 0; q < 4; q++) acc[i][j][q] = 0.0f;

        const uint32_t bbuf0 = abase + OFF2_B + p * 32768;
        #pragma unroll
        for (int ks = 0; ks < 4; ks++) {
            const int kb = ks * 16 + k_off;
            uint32_t a0f[2][4], a1f[2][4];
            #pragma unroll
            for (int i = 0; i < 2; i++) {
                uint32_t ao = abase + SWZ((a_row + i * 16) * 128 + kb * 2);
                LDSM_X4(a0f[i], ao);
                LDSM_X4(a1f[i], ao + OFF2_A1);
            }
            #pragma unroll
            for (int j2 = 0; j2 < 4; j2++) {
                uint32_t bo = bbuf0 + SWZ((b_rowL + j2 * 16) * 128 + kb * 2);
                uint32_t b0r[4], b1r[4];
                LDSM_X4(b0r, bo);
                LDSM_X4(b1r, bo + 16384);
                #pragma unroll
                for (int sub = 0; sub < 2; sub++)
                    #pragma unroll
                    for (int i = 0; i < 2; i++) {
                        MMA_16816(acc[i][j2 * 2 + sub], a0f[i], b0r[sub], b0r[2 + sub]);
                        MMA_16816(acc[i][j2 * 2 + sub], a0f[i], b1r[sub], b1r[2 + sub]);
                        MMA_16816(acc[i][j2 * 2 + sub], a1f[i], b0r[sub], b0r[2 + sub]);
                    }
            }
        }

        #pragma unroll
        for (int i = 0; i < 2; i++) {
            #pragma unroll
            for (int j = 0; j < 8; j++) {
                int cbase = n0 + cn0 + j * 8 + (lane & 3) * 2;
                #pragma unroll
                for (int h = 0; h < 2; h++) {
                    int s = i * 2 + h;
                    float va = acc[i][j][2 * h + 0];
                    float vb = acc[i][j][2 * h + 1];
                    if (va > bv[s]) { bv[s] = va; bi[s] = cbase; }
                    if (vb > bv[s]) { bv[s] = vb; bi[s] = cbase + 1; }
                }
            }
        }
        __syncthreads();
    }

    #pragma unroll
    for (int s = 0; s < 4; s++) {
        #pragma unroll
        for (int off = 1; off < 4; off <<= 1) {
            float ov = __shfl_xor_sync(0xFFFFFFFFu, bv[s], off);
            int   oi = __shfl_xor_sync(0xFFFFFFFFu, bi[s], off);
            if (ov > bv[s] || (ov == bv[s] && oi < bi[s])) { bv[s] = ov; bi[s] = oi; }
        }
    }

    float2* table = (float2*)(sm + OFF2_TAB);
    if ((lane & 3) == 0) {
        #pragma unroll
        for (int s = 0; s < 4; s++) {
            int row = wm0 + (s >> 1) * 16 + (s & 1) * 8 + (lane >> 2);
            table[row * 2 + warp_n] = make_float2(bv[s], __int_as_float(bi[s]));
        }
    }
    __syncthreads();

    if (tid < 256 && base + tid < count) {
        float2 r0 = table[tid * 2 + 0];
        float2 r1 = table[tid * 2 + 1];
        float best = r0.x;
        int besti  = __float_as_int(r0.y);
        int i1     = __float_as_int(r1.y);
        if (r1.x > best || (r1.x == best && i1 < besti)) { best = r1.x; besti = i1; }
        unsigned long long packed =
            ((unsigned long long)fkey(best) << 13) | (unsigned long long)(8191 - besti);
        atomicMax(&g_best[s_tok[tid]], packed);
    }

    // last-split-in resolves this token-tile
    __threadfence();
    __syncthreads();
    if (tid == 0) s_last = atomicAdd(&g_cnt[mt], 1);
    __syncthreads();
    if (s_last == 15 && tid < 256 && base + tid < count) {
        int tok = s_tok[tid];
        unsigned long long p = g_best[tok];
        int bi2 = 8191 - (int)(p & 0x1FFFull);
        g_idx[tok] = bi2;
        atomicAdd(&g_hist[bi2], 1);
        idx_out_f[tok] = (float)bi2;
    }
}

// ---------------------------------------------------------------------------
// Kernel 4: gather z_q into out, per-block loss partials (8 elems/thread)
// ---------------------------------------------------------------------------
__global__ __launch_bounds__(256)
void vq_gather_loss(const float* __restrict__ z, const float* __restrict__ emb,
                    float* __restrict__ out) {
    int v = blockIdx.x * 256 + threadIdx.x;
    int e = v << 3;                      // 8 consecutive elements, same (b, c)
    int c = (e >> 12) & 63;
    int t = ((e >> 18) << 12) | (e & 4095);

    float4 zv0 = *(const float4*)(z + e);
    float4 zv1 = *(const float4*)(z + e + 4);
    int ii[8];
    #pragma unroll
    for (int q = 0; q < 8; q++) ii[q] = g_idx[t + q];
    float qq[8];
    #pragma unroll
    for (int q = 0; q < 8; q++) qq[q] = emb[ii[q] * EMBED_DIM + c];
    *(float4*)(out + e)     = make_float4(qq[0], qq[1], qq[2], qq[3]);
    *(float4*)(out + e + 4) = make_float4(qq[4], qq[5], qq[6], qq[7]);

    float zz[8] = {zv0.x, zv0.y, zv0.z, zv0.w, zv1.x, zv1.y, zv1.z, zv1.w};
    float s = 0.0f;
    #pragma unroll
    for (int q = 0; q < 8; q++) {
        float d = qq[q] - zz[q];
        s += d * d;
    }

    #pragma unroll
    for (int o = 16; o > 0; o >>= 1) s += __shfl_xor_sync(0xFFFFFFFFu, s, o);
    __shared__ float ws[8];
    int lane = threadIdx.x & 31, wrp = threadIdx.x >> 5;
    if (lane == 0) ws[wrp] = s;
    __syncthreads();
    if (threadIdx.x == 0) {
        float acc = 0.0f;
        #pragma unroll
        for (int i = 0; i < 8; i++) acc += ws[i];
        g_partial[blockIdx.x] = acc;
    }
}

// ---------------------------------------------------------------------------
// Kernel 5: finalize loss + perplexity
// ---------------------------------------------------------------------------
__global__ __launch_bounds__(256)
void vq_finalize(float* __restrict__ out) {
    __shared__ float sh[256];
    int tid = threadIdx.x;

    float s = 0.0f;
    for (int i = tid; i < N_PART; i += 256) s += g_partial[i];
    sh[tid] = s;
    __syncthreads();
    for (int o = 128; o > 0; o >>= 1) {
        if (tid < o) sh[tid] += sh[tid + o];
        __syncthreads();
    }
    if (tid == 0) out[N_ELEM] = 1.25f * sh[0] / (float)N_ELEM;
    __syncthreads();

    float h = 0.0f;
    for (int i = tid; i < NUM_EMBED; i += 256) {
        float p = (float)g_hist[i] * (1.0f / (float)N_TOK);
        h += p * logf(p + 1e-10f);
    }
    sh[tid] = h;
    __syncthreads();
    for (int o = 128; o > 0; o >>= 1) {
        if (tid < o) sh[tid] += sh[tid + o];
        __syncthreads();
    }
    if (tid == 0) out[N_ELEM + 1] = expf(-sh[0]);
}

// ---------------------------------------------------------------------------
// Output layout (all float32): [0, N_ELEM) out | loss | perplexity | idx_map
// ---------------------------------------------------------------------------
extern "C" void kernel_launch(void* const* d_in, const int* in_sizes, int n_in,
                              void* d_out, int out_size) {
    const float* z   = (const float*)d_in[0];
    const float* emb = (const float*)d_in[1];
    float* out = (float*)d_out;

    cudaFuncSetAttribute(vq_argmax_mma, cudaFuncAttributeMaxDynamicSharedMemorySize,
                         SMEM1_BYTES);
    cudaFuncSetAttribute(vq_rescan_mma, cudaFuncAttributeMaxDynamicSharedMemorySize,
                         SMEM2_BYTES);

    vq_prep_embed<<<1024, 256>>>(emb);
    vq_argmax_mma<<<N_TOK / M_CTA, NT1, SMEM1_BYTES>>>(z, out + N_ELEM + 2);
    vq_rescan_mma<<<512, NT2, SMEM2_BYTES>>>(z, out + N_ELEM + 2);
    vq_gather_loss<<<N_ELEM / 2048, 256>>>(z, emb, out);
    vq_finalize<<<1, 256>>>(out);
}

// round 12
// speedup vs baseline: 1.0438x; 1.0438x over previous
#include <cuda_runtime.h>
#include <cuda_fp16.h>
#include <math.h>
#include <stdint.h>

#define NUM_EMBED 8192
#define EMBED_DIM 64
#define BB 8
#define HH 64
#define WW 64
#define N_TOK   (BB*HH*WW)            /* 32768 */
#define N_ELEM  (BB*EMBED_DIM*HH*WW)  /* 2097152 */
#define HW      (HH*WW)               /* 4096 */
#define N_PART  2048

#define M_CTA   128                   /* tokens per CTA (stage 1) */
#define TN      128                   /* codes per tile */
#define N_TILES (NUM_EMBED / TN)      /* 64 */
#define NT1     256                   /* stage-1 threads (8 warps) */
#define NT2     512                   /* stage-2 threads */

// stage-1 SMEM (from 1024-aligned base):
//   A0  @ 0     : 128 rows x 128B (fp16 z, swizzled)   16384
//   B   @ 16384 : 2 bufs x [128 x 128B]                32768
//   TAB @ 49152 : 128 x 2 float4                        4096
#define OFF_B    16384
#define OFF_TAB  49152
#define SMEM1_BYTES (OFF_TAB + 4096 + 1024)

// stage-2 SMEM:
//   A0 @ 0, A1 @ 32768 (256 rows x 128B each)
//   B  @ 65536 : 2 bufs x 2 terms x 16KB = 65536
//   TAB@ 131072: 256 x 2 float2 = 4096; TOK @ 135168: 1KB
#define OFF2_A1  32768
#define OFF2_B   65536
#define OFF2_TAB 131072
#define OFF2_TOK 135168
#define SMEM2_BYTES (OFF2_TOK + 1024 + 1024)

#define SWZ(o) ((o) ^ (((o) >> 3) & 0x70))

// ---------------------------------------------------------------------------
// device scratch
// ---------------------------------------------------------------------------
__device__ __align__(16) __half g_e0[NUM_EMBED * EMBED_DIM];
__device__ __align__(16) __half g_e1[NUM_EMBED * EMBED_DIM];
__device__ __align__(16) float  g_enf[NUM_EMBED * EMBED_DIM];
__device__ int   g_idx[N_TOK];
__device__ int   g_flist[N_TOK];
__device__ int   g_nflag;
__device__ unsigned long long g_best[N_TOK];
__device__ int   g_hist[NUM_EMBED];
__device__ float g_partial[N_PART];

// ---------------------------------------------------------------------------
// asm helpers (plain sm_80+ only)
// ---------------------------------------------------------------------------
__device__ __forceinline__ uint32_t smem_u32(const void* p) {
    uint32_t a;
    asm("{ .reg .u64 t; cvta.to.shared.u64 t, %1; cvt.u32.u64 %0, t; }" : "=r"(a) : "l"(p));
    return a;
}
#define LDSM_X4(r, addr)                                                         \
    asm volatile("ldmatrix.sync.aligned.m8n8.x4.shared.b16 {%0,%1,%2,%3}, [%4];" \
        : "=r"((r)[0]), "=r"((r)[1]), "=r"((r)[2]), "=r"((r)[3]) : "r"(addr))

#define MMA_16816(c, a, b0, b1)                                                  \
    asm volatile("mma.sync.aligned.m16n8k16.row.col.f32.f16.f16.f32 "            \
        "{%0,%1,%2,%3}, {%4,%5,%6,%7}, {%8,%9}, {%0,%1,%2,%3};"                  \
        : "+f"((c)[0]), "+f"((c)[1]), "+f"((c)[2]), "+f"((c)[3])                 \
        : "r"((a)[0]), "r"((a)[1]), "r"((a)[2]), "r"((a)[3]), "r"(b0), "r"(b1))

#define CP_ASYNC16(saddr, gptr)                                                  \
    asm volatile("cp.async.cg.shared.global [%0], [%1], 16;" :: "r"(saddr), "l"(gptr))
#define CP_COMMIT()  asm volatile("cp.async.commit_group;")
#define CP_WAIT1()   asm volatile("cp.async.wait_group 1;")
#define CP_WAIT0()   asm volatile("cp.async.wait_group 0;")

__device__ __forceinline__ uint32_t fkey(float v) {
    uint32_t u = __float_as_uint(v);
    return (u & 0x80000000u) ? ~u : (u | 0x80000000u);
}

// ---------------------------------------------------------------------------
// Kernel 1: zero scratch + normalize codebook -> fp16 x2 split + fp32
// ---------------------------------------------------------------------------
__global__ void vq_prep_embed(const float* __restrict__ emb) {
    int gid = blockIdx.x * 256 + threadIdx.x;
    if (threadIdx.x < 8) g_hist[blockIdx.x * 8 + threadIdx.x] = 0;
    if (gid < N_TOK) g_best[gid] = 0ull;
    if (gid == 0) g_nflag = 0;

    int wid  = gid >> 5;
    int lane = threadIdx.x & 31;
    if (wid >= NUM_EMBED) return;
    const float* row = emb + wid * EMBED_DIM;
    float x0 = row[lane];
    float x1 = row[lane + 32];
    float s = x0 * x0 + x1 * x1;
    #pragma unroll
    for (int o = 16; o > 0; o >>= 1) s += __shfl_xor_sync(0xFFFFFFFFu, s, o);
    float inv = 1.0f / sqrtf(s);
    #pragma unroll
    for (int h = 0; h < 2; h++) {
        int c = lane + h * 32;
        float xn = (h ? x1 : x0) * inv;
        __half h0 = __float2half(xn);
        __half h1 = __float2half(xn - __half2float(h0));
        g_e0[wid * EMBED_DIM + c]  = h0;
        g_e1[wid * EMBED_DIM + c]  = h1;
        g_enf[wid * EMBED_DIM + c] = xn;
    }
}

// ---------------------------------------------------------------------------
// Kernel 2 (stage 1): 1-term fp16 GEMM + screened top-2 + certificate.
// 256 threads = 8 warps, 4(M) x 2(N). Warp tile 32 x 64. 2 CTAs/SM.
// Epilogue: per-slot tile-max screen; detailed top-2 only when it can matter.
// ---------------------------------------------------------------------------
__global__ __launch_bounds__(NT1, 2)
void vq_argmax_mma(const float* __restrict__ z, float* __restrict__ idx_out_f) {
    extern __shared__ char dsm_raw[];
    const uint32_t raw   = smem_u32(dsm_raw);
    const uint32_t abase = (raw + 1023u) & ~1023u;
    char* sm = dsm_raw + (abase - raw);

    const int tid    = threadIdx.x;
    const int wid    = tid >> 5;
    const int lane   = tid & 31;
    const int warp_m = wid & 3;
    const int warp_n = wid >> 2;
    const int wm0    = warp_m * 32;
    const int cn0    = warp_n * 64;
    const int grp    = lane >> 3;

    const int m0  = blockIdx.x * M_CTA;
    const int b   = m0 >> 12;
    const int hw0 = m0 & 4095;

    auto load_b = [&](int t, int p) {
        const int n0 = t * TN;
        const uint32_t sb = abase + OFF_B + p * 16384;
        #pragma unroll
        for (int q = 0; q < 4; q++) {
            int i  = tid + q * NT1;        // 0..1023
            int r  = i >> 3;
            int ch = i & 7;
            CP_ASYNC16(sb + SWZ(r * 128 + ch * 16),
                       g_e0 + (n0 + r) * EMBED_DIM + ch * 8);
        }
    };

    load_b(0, 0);
    CP_COMMIT();

    // prologue: z tile -> fp16 A0 (swizzled)
    {
        const float* zb = z + b * (EMBED_DIM * HW) + hw0;
        #pragma unroll
        for (int q = 0; q < 8; q++) {
            int i  = tid + q * NT1;        // 0..2047
            int c  = i >> 5;
            int m4 = (i & 31) << 2;
            float4 v = *(const float4*)(zb + c * HW + m4);
            float xs[4] = {v.x, v.y, v.z, v.w};
            #pragma unroll
            for (int e = 0; e < 4; e++)
                *(__half*)(sm + SWZ((m4 + e) * 128 + c * 2)) = __float2half(xs[e]);
        }
    }
    __syncthreads();

    float v1[4], v2[4];
    int   vi[4];
    #pragma unroll
    for (int s = 0; s < 4; s++) { v1[s] = -3.0e38f; v2[s] = -3.0e38f; vi[s] = 0x7FFFFFFF; }

    const int a_row  = wm0 + (grp & 1) * 8 + (lane & 7);
    const int b_rowL = cn0 + (grp & 1) * 8 + (lane & 7);
    const int k_off  = (grp >> 1) * 8;

    for (int t = 0; t < N_TILES; t++) {
        const int p  = t & 1;
        const int n0 = t * TN;

        if (t + 1 < N_TILES) {
            load_b(t + 1, (t + 1) & 1);
            CP_COMMIT();
            CP_WAIT1();
        } else {
            CP_WAIT0();
        }
        __syncthreads();

        float acc[2][8][4];
        #pragma unroll
        for (int i = 0; i < 2; i++)
            #pragma unroll
            for (int j = 0; j < 8; j++)
                #pragma unroll
                for (int q = 0; q < 4; q++) acc[i][j][q] = 0.0f;

        const uint32_t bbuf = abase + OFF_B + p * 16384;
        #pragma unroll
        for (int ks = 0; ks < 4; ks++) {
            const int kb = ks * 16 + k_off;
            uint32_t a0f[2][4];
            #pragma unroll
            for (int i = 0; i < 2; i++)
                LDSM_X4(a0f[i], abase + SWZ((a_row + i * 16) * 128 + kb * 2));
            #pragma unroll
            for (int j2 = 0; j2 < 4; j2++) {
                uint32_t b0r[4];
                LDSM_X4(b0r, bbuf + SWZ((b_rowL + j2 * 16) * 128 + kb * 2));
                #pragma unroll
                for (int sub = 0; sub < 2; sub++)
                    #pragma unroll
                    for (int i = 0; i < 2; i++)
                        MMA_16816(acc[i][j2 * 2 + sub], a0f[i], b0r[sub], b0r[2 + sub]);
            }
        }

        // --- phase 1: cheap per-slot tile max (pure fmax tree) ---
        float tm[4];
        #pragma unroll
        for (int s = 0; s < 4; s++) tm[s] = -3.0e38f;
        #pragma unroll
        for (int i = 0; i < 2; i++)
            #pragma unroll
            for (int j = 0; j < 8; j++)
                #pragma unroll
                for (int h = 0; h < 2; h++)
                    tm[i * 2 + h] = fmaxf(tm[i * 2 + h],
                                          fmaxf(acc[i][j][2 * h], acc[i][j][2 * h + 1]));

        // --- phase 2: detailed top-2 only if this tile can change (v1,v2) ---
        // If tm <= v2: no score here exceeds the running 2nd max, so the
        // round-10 update logic would leave v1/v2/vi unchanged (strict >,
        // ascending indices). Skipping is exact.
        #pragma unroll
        for (int i = 0; i < 2; i++) {
            #pragma unroll
            for (int h = 0; h < 2; h++) {
                int s = i * 2 + h;
                if (tm[s] > v2[s]) {
                    #pragma unroll
                    for (int j = 0; j < 8; j++) {
                        int cbase = n0 + cn0 + j * 8 + (lane & 3) * 2;
                        float va = acc[i][j][2 * h + 0];
                        float vb = acc[i][j][2 * h + 1];
                        float hi = fmaxf(va, vb);
                        float lo = fminf(va, vb);
                        int   hidx = (vb > va) ? (cbase + 1) : cbase;
                        if (hi > v1[s]) {
                            v2[s] = fmaxf(v1[s], lo);
                            v1[s] = hi;
                            vi[s] = hidx;
                        } else {
                            v2[s] = fmaxf(v2[s], hi);
                        }
                    }
                }
            }
        }
        __syncthreads();
    }

    // quad reduce with top-2 merge
    #pragma unroll
    for (int s = 0; s < 4; s++) {
        #pragma unroll
        for (int off = 1; off < 4; off <<= 1) {
            float ov1 = __shfl_xor_sync(0xFFFFFFFFu, v1[s], off);
            int   oi1 = __shfl_xor_sync(0xFFFFFFFFu, vi[s], off);
            float ov2 = __shfl_xor_sync(0xFFFFFFFFu, v2[s], off);
            if (ov1 > v1[s] || (ov1 == v1[s] && oi1 < vi[s])) {
                v2[s] = fmaxf(fmaxf(v1[s], ov2), v2[s]);
                v1[s] = ov1; vi[s] = oi1;
            } else {
                v2[s] = fmaxf(fmaxf(v2[s], ov1), ov2);
            }
        }
    }

    float4* table = (float4*)(sm + OFF_TAB);
    if ((lane & 3) == 0) {
        #pragma unroll
        for (int s = 0; s < 4; s++) {
            int row = wm0 + (s >> 1) * 16 + (s & 1) * 8 + (lane >> 2);
            table[row * 2 + warp_n] =
                make_float4(v1[s], __int_as_float(vi[s]), v2[s], 0.0f);
        }
    }
    __syncthreads();

    if (tid < M_CTA) {
        float4 r0 = table[tid * 2 + 0];
        float4 r1 = table[tid * 2 + 1];
        float fv2; int fi1;
        int i0 = __float_as_int(r0.y), i1 = __float_as_int(r1.y);
        if (r1.x > r0.x || (r1.x == r0.x && i1 < i0)) {
            fi1 = i1; fv2 = fmaxf(r0.x, r1.z);
        } else {
            fi1 = i0; fv2 = fmaxf(r1.x, r0.z);
        }

        // exact fp32 rescore of fi1 (z re-read from L2) + ||z||^2
        const float* zb2 = z + b * (EMBED_DIM * HW) + hw0 + tid;
        const float4* er = (const float4*)(g_enf + fi1 * EMBED_DIM);
        float acc = 0.0f, accn = 0.0f;
        #pragma unroll
        for (int q = 0; q < 16; q++) {
            float4 ev = er[q];
            float z0 = zb2[(q * 4 + 0) * HW];
            float z1 = zb2[(q * 4 + 1) * HW];
            float z2 = zb2[(q * 4 + 2) * HW];
            float z3 = zb2[(q * 4 + 3) * HW];
            acc  += z0 * ev.x + z1 * ev.y + z2 * ev.z + z3 * ev.w;
            accn += z0 * z0 + z1 * z1 + z2 * z2 + z3 * z3;
        }
        float eps = 5.2e-4f * sqrtf(accn) + 1.0e-5f;

        int token = m0 + tid;
        g_idx[token] = fi1;
        if (acc > fv2 + eps) {
            atomicAdd(&g_hist[fi1], 1);
            idx_out_f[token] = (float)fi1;
        } else {
            int pos = atomicAdd(&g_nflag, 1);
            g_flist[pos] = token;
        }
    }
}

// ---------------------------------------------------------------------------
// Kernel 3 (stage 2): 3-term mma rescan of flagged tokens.
// grid 512 = 32 token-tiles x 16 codebook splits (512 codes each).
// ---------------------------------------------------------------------------
__global__ __launch_bounds__(NT2, 1)
void vq_rescan_mma(const float* __restrict__ z) {
    const int count = g_nflag;
    const int mt = blockIdx.x >> 4;
    const int sp = blockIdx.x & 15;
    const int base = mt * 256;
    if (base >= count) return;

    extern __shared__ char dsm_raw[];
    const uint32_t raw   = smem_u32(dsm_raw);
    const uint32_t abase = (raw + 1023u) & ~1023u;
    char* sm = dsm_raw + (abase - raw);
    int* s_tok = (int*)(sm + OFF2_TOK);

    const int tid    = threadIdx.x;
    const int wid    = tid >> 5;
    const int lane   = tid & 31;
    const int warp_m = wid & 7;
    const int warp_n = wid >> 3;
    const int wm0    = warp_m * 32;
    const int cn0    = warp_n * 64;
    const int grp    = lane >> 3;
    const int nbase  = sp * 512;

    auto load_b = [&](int t, int p) {
        const int n0 = nbase + t * TN;
        const uint32_t sb = abase + OFF2_B + p * 32768;
        #pragma unroll
        for (int q = 0; q < 4; q++) {
            int i    = tid + q * NT2;
            int term = i >> 10;
            int rq   = i & 1023;
            int r    = rq >> 3;
            int ch   = rq & 7;
            const __half* src = term ? g_e1 : g_e0;
            CP_ASYNC16(sb + term * 16384 + SWZ(r * 128 + ch * 16),
                       src + (n0 + r) * EMBED_DIM + ch * 8);
        }
    };

    if (tid < 256) s_tok[tid] = g_flist[min(base + tid, count - 1)];

    load_b(0, 0);
    CP_COMMIT();
    __syncthreads();

    {
        int row  = tid >> 1;
        int half = tid & 1;
        int tok  = s_tok[row];
        const float* zb = z + (tok >> 12) * (EMBED_DIM * HW) + (tok & 4095);
        #pragma unroll
        for (int q = 0; q < 32; q++) {
            int c = half * 32 + q;
            float x = zb[c * HW];
            __half h0 = __float2half(x);
            __half h1 = __float2half(x - __half2float(h0));
            int off = SWZ(row * 128 + c * 2);
            *(__half*)(sm + off)           = h0;
            *(__half*)(sm + OFF2_A1 + off) = h1;
        }
    }
    __syncthreads();

    float bv[4];
    int   bi[4];
    #pragma unroll
    for (int s = 0; s < 4; s++) { bv[s] = -3.0e38f; bi[s] = 0x7FFFFFFF; }

    const int a_row  = wm0 + (grp & 1) * 8 + (lane & 7);
    const int b_rowL = cn0 + (grp & 1) * 8 + (lane & 7);
    const int k_off  = (grp >> 1) * 8;

    for (int t = 0; t < 4; t++) {
        const int p  = t & 1;
        const int n0 = nbase + t * TN;

        if (t + 1 < 4) {
            load_b(t + 1, (t + 1) & 1);
            CP_COMMIT();
            CP_WAIT1();
        } else {
            CP_WAIT0();
        }
        __syncthreads();

        float acc[2][8][4];
        #pragma unroll
        for (int i = 0; i < 2; i++)
            #pragma unroll
            for (int j = 0; j < 8; j++)
                #pragma unroll
                for (int q = 0; q < 4; q++) acc[i][j][q] = 0.0f;

        const uint32_t bbuf0 = abase + OFF2_B + p * 32768;
        #pragma unroll
        for (int ks = 0; ks < 4; ks++) {
            const int kb = ks * 16 + k_off;
            uint32_t a0f[2][4], a1f[2][4];
            #pragma unroll
            for (int i = 0; i < 2; i++) {
                uint32_t ao = abase + SWZ((a_row + i * 16) * 128 + kb * 2);
                LDSM_X4(a0f[i], ao);
                LDSM_X4(a1f[i], ao + OFF2_A1);
            }
            #pragma unroll
            for (int j2 = 0; j2 < 4; j2++) {
                uint32_t bo = bbuf0 + SWZ((b_rowL + j2 * 16) * 128 + kb * 2);
                uint32_t b0r[4], b1r[4];
                LDSM_X4(b0r, bo);
                LDSM_X4(b1r, bo + 16384);
                #pragma unroll
                for (int sub = 0; sub < 2; sub++)
                    #pragma unroll
                    for (int i = 0; i < 2; i++) {
                        MMA_16816(acc[i][j2 * 2 + sub], a0f[i], b0r[sub], b0r[2 + sub]);
                        MMA_16816(acc[i][j2 * 2 + sub], a0f[i], b1r[sub], b1r[2 + sub]);
                        MMA_16816(acc[i][j2 * 2 + sub], a1f[i], b0r[sub], b0r[2 + sub]);
                    }
            }
        }

        #pragma unroll
        for (int i = 0; i < 2; i++) {
            #pragma unroll
            for (int j = 0; j < 8; j++) {
                int cbase = n0 + cn0 + j * 8 + (lane & 3) * 2;
                #pragma unroll
                for (int h = 0; h < 2; h++) {
                    int s = i * 2 + h;
                    float va = acc[i][j][2 * h + 0];
                    float vb = acc[i][j][2 * h + 1];
                    if (va > bv[s]) { bv[s] = va; bi[s] = cbase; }
                    if (vb > bv[s]) { bv[s] = vb; bi[s] = cbase + 1; }
                }
            }
        }
        __syncthreads();
    }

    #pragma unroll
    for (int s = 0; s < 4; s++) {
        #pragma unroll
        for (int off = 1; off < 4; off <<= 1) {
            float ov = __shfl_xor_sync(0xFFFFFFFFu, bv[s], off);
            int   oi = __shfl_xor_sync(0xFFFFFFFFu, bi[s], off);
            if (ov > bv[s] || (ov == bv[s] && oi < bi[s])) { bv[s] = ov; bi[s] = oi; }
        }
    }

    float2* table = (float2*)(sm + OFF2_TAB);
    if ((lane & 3) == 0) {
        #pragma unroll
        for (int s = 0; s < 4; s++) {
            int row = wm0 + (s >> 1) * 16 + (s & 1) * 8 + (lane >> 2);
            table[row * 2 + warp_n] = make_float2(bv[s], __int_as_float(bi[s]));
        }
    }
    __syncthreads();

    if (tid < 256 && base + tid < count) {
        float2 r0 = table[tid * 2 + 0];
        float2 r1 = table[tid * 2 + 1];
        float best = r0.x;
        int besti  = __float_as_int(r0.y);
        int i1     = __float_as_int(r1.y);
        if (r1.x > best || (r1.x == best && i1 < besti)) { best = r1.x; besti = i1; }
        unsigned long long packed =
            ((unsigned long long)fkey(best) << 13) | (unsigned long long)(8191 - besti);
        atomicMax(&g_best[s_tok[tid]], packed);
    }
}

// ---------------------------------------------------------------------------
// Kernel 4: write flagged-token results (grid-stride, 32 blocks)
// ---------------------------------------------------------------------------
__global__ __launch_bounds__(256)
void vq_resolve_write(float* __restrict__ idx_out_f) {
    for (int i = blockIdx.x * 256 + threadIdx.x; i < g_nflag; i += 32 * 256) {
        int tok = g_flist[i];
        unsigned long long p = g_best[tok];
        int bi = 8191 - (int)(p & 0x1FFFull);
        g_idx[tok] = bi;
        atomicAdd(&g_hist[bi], 1);
        idx_out_f[tok] = (float)bi;
    }
}

// ---------------------------------------------------------------------------
// Kernel 5: gather z_q into out, per-block loss partials
// ---------------------------------------------------------------------------
__global__ __launch_bounds__(256)
void vq_gather_loss(const float* __restrict__ z, const float* __restrict__ emb,
                    float* __restrict__ out) {
    int v = blockIdx.x * 256 + threadIdx.x;
    int e = v << 2;
    int c = (e >> 12) & 63;
    int t = ((e >> 18) << 12) | (e & 4095);

    float4 zv = *(const float4*)(z + e);
    int i0 = g_idx[t + 0];
    int i1 = g_idx[t + 1];
    int i2 = g_idx[t + 2];
    int i3 = g_idx[t + 3];
    float q0 = emb[i0 * EMBED_DIM + c];
    float q1 = emb[i1 * EMBED_DIM + c];
    float q2 = emb[i2 * EMBED_DIM + c];
    float q3 = emb[i3 * EMBED_DIM + c];
    *(float4*)(out + e) = make_float4(q0, q1, q2, q3);

    float d0 = q0 - zv.x, d1 = q1 - zv.y, d2 = q2 - zv.z, d3 = q3 - zv.w;
    float s = d0 * d0 + d1 * d1 + d2 * d2 + d3 * d3;

    #pragma unroll
    for (int o = 16; o > 0; o >>= 1) s += __shfl_xor_sync(0xFFFFFFFFu, s, o);
    __shared__ float ws[8];
    int lane = threadIdx.x & 31, wrp = threadIdx.x >> 5;
    if (lane == 0) ws[wrp] = s;
    __syncthreads();
    if (threadIdx.x == 0) {
        float acc = 0.0f;
        #pragma unroll
        for (int i = 0; i < 8; i++) acc += ws[i];
        g_partial[blockIdx.x] = acc;
    }
}

// ---------------------------------------------------------------------------
// Kernel 6: finalize loss + perplexity
// ---------------------------------------------------------------------------
__global__ __launch_bounds__(256)
void vq_finalize(float* __restrict__ out) {
    __shared__ float sh[256];
    int tid = threadIdx.x;

    float s = 0.0f;
    for (int i = tid; i < N_PART; i += 256) s += g_partial[i];
    sh[tid] = s;
    __syncthreads();
    for (int o = 128; o > 0; o >>= 1) {
        if (tid < o) sh[tid] += sh[tid + o];
        __syncthreads();
    }
    if (tid == 0) out[N_ELEM] = 1.25f * sh[0] / (float)N_ELEM;
    __syncthreads();

    float h = 0.0f;
    for (int i = tid; i < NUM_EMBED; i += 256) {
        float p = (float)g_hist[i] * (1.0f / (float)N_TOK);
        h += p * logf(p + 1e-10f);
    }
    sh[tid] = h;
    __syncthreads();
    for (int o = 128; o > 0; o >>= 1) {
        if (tid < o) sh[tid] += sh[tid + o];
        __syncthreads();
    }
    if (tid == 0) out[N_ELEM + 1] = expf(-sh[0]);
}

// ---------------------------------------------------------------------------
// Output layout (all float32): [0, N_ELEM) out | loss | perplexity | idx_map
// ---------------------------------------------------------------------------
extern "C" void kernel_launch(void* const* d_in, const int* in_sizes, int n_in,
                              void* d_out, int out_size) {
    const float* z   = (const float*)d_in[0];
    const float* emb = (const float*)d_in[1];
    float* out = (float*)d_out;

    cudaFuncSetAttribute(vq_argmax_mma, cudaFuncAttributeMaxDynamicSharedMemorySize,
                         SMEM1_BYTES);
    cudaFuncSetAttribute(vq_rescan_mma, cudaFuncAttributeMaxDynamicSharedMemorySize,
                         SMEM2_BYTES);

    vq_prep_embed<<<1024, 256>>>(emb);
    vq_argmax_mma<<<N_TOK / M_CTA, NT1, SMEM1_BYTES>>>(z, out + N_ELEM + 2);
    vq_rescan_mma<<<512, NT2, SMEM2_BYTES>>>(z);
    vq_resolve_write<<<32, 256>>>(out + N_ELEM + 2);
    vq_gather_loss<<<N_PART, 256>>>(z, emb, out);
    vq_finalize<<<1, 256>>>(out);
}